// round 12
// baseline (speedup 1.0000x reference)
#include <cuda_runtime.h>
#include <cuda_bf16.h>
#include <cstdint>

#define LAMBDA_COORD 5.0f
#define LAMBDA_NOOBJ 0.5f
#define EPS 1e-9f
#define WPB 6                   // warps per block (192 threads)
#define BPSM 4                  // blocks per SM
#define NBLK (148 * BPSM)       // one resident wave = 592 blocks
#define NSTAGE 2                // cp.async stages per warp
#define STAGE_BYTES 4096        // one batch pair (2 x 2KB slabs)

__device__ double g_partial[NBLK];
__device__ unsigned g_count = 0;

__device__ __forceinline__ void cp_async16(uint32_t saddr, const void* g) {
    asm volatile("cp.async.cg.shared.global [%0], [%1], 16;" :: "r"(saddr), "l"(g));
}
__device__ __forceinline__ void cp_commit() {
    asm volatile("cp.async.commit_group;");
}
template <int N>
__device__ __forceinline__ void cp_wait() {
    asm volatile("cp.async.wait_group %0;" :: "n"(N));
}

__device__ __forceinline__ float bbox_iou(float px, float py, float pr,
                                          float gx, float gy, float gr) {
    float l1 = px - pr, r1 = px + pr, t1 = py - pr, b1 = py + pr;
    float l2 = gx - gr, r2 = gx + gr, t2 = gy - gr, b2 = gy + gr;
    float iw = fmaxf(fminf(r1, r2) - fmaxf(l1, l2), 0.0f);
    float ih = fmaxf(fminf(b1, b2) - fmaxf(t1, t2), 0.0f);
    float inter = iw * ih;
    float a1 = (r1 - l1) * (b1 - t1);
    float a2 = (r2 - l2) * (b2 - t2);
    return inter / (a1 + a2 - inter + EPS);
}

__global__ void __launch_bounds__(WPB * 32, BPSM)
yolo_loss_kernel(const float* __restrict__ pred,
                 const int*   __restrict__ label_rc,
                 const float* __restrict__ label_box,
                 int B, float* __restrict__ out) {
    // Dynamic smem: WPB * NSTAGE * 4KB = 48 KB exactly (no opt-in needed).
    // No static shared; reduction scratch aliases into this buffer post-loop.
    extern __shared__ float dsh[];

    const int warp = threadIdx.x >> 5;
    const int lane = threadIdx.x & 31;
    const int TW = NBLK * WPB;           // total warps = 3552
    const int P = (B + 1) >> 1;          // batch pairs
    const int p0 = blockIdx.x * WPB + warp;

    const int li   = lane & 15;          // label index within batch
    const int half = lane >> 4;          // 0 = batch A, 1 = batch B

    uint32_t s_base = (uint32_t)__cvta_generic_to_shared(dsh)
                    + (uint32_t)warp * (NSTAGE * STAGE_BYTES);
    float4* wbase4 = reinterpret_cast<float4*>(dsh) + warp * (NSTAGE * 256);

    const float4 zero4 = make_float4(0.f, 0.f, 0.f, 0.f);

    float acc  = 0.0f;   // coord + conf (weighted)
    float nsum = 0.0f;   // c3^2+c7^2 over ALL cells
    float nsub = 0.0f;   // over distinct object cells

    // issue one pair's 8 cp.asyncs into stage st (zero-fill missing batch B)
    auto issue = [&](int st, int pp) {
        if (pp < P) {
            uint32_t sa = s_base + st * STAGE_BYTES + lane * 16;
            const char* g = (const char*)pred + (size_t)pp * 4096 + lane * 16;
            cp_async16(sa,        g);
            cp_async16(sa + 512,  g + 512);
            cp_async16(sa + 1024, g + 1024);
            cp_async16(sa + 1536, g + 1536);
            if (2 * pp + 1 < B) {
                cp_async16(sa + 2048, g + 2048);
                cp_async16(sa + 2560, g + 2560);
                cp_async16(sa + 3072, g + 3072);
                cp_async16(sa + 3584, g + 3584);
            } else {
                float4* stg = wbase4 + st * 256;
                stg[128 + lane] = zero4; stg[160 + lane] = zero4;
                stg[192 + lane] = zero4; stg[224 + lane] = zero4;
            }
        }
        cp_commit();
    };

    // prologue: fill both stages
    issue(0, p0);
    issue(1, p0 + TW);

    // label prefetch for first pair (full warp: 16 labels x 2 batches)
    int2 nrc = make_int2(0, 0);
    float ngx = 0.f, ngy = 0.f, ngr = 0.f;
    bool nval = false;
    if (p0 < P) {
        int bb = 2 * p0 + half;
        if (bb < B) {
            nval = true;
            nrc = reinterpret_cast<const int2*>(label_rc)[(size_t)bb * 16 + li];
            const float* bx = label_box + ((size_t)bb * 16 + li) * 3;
            ngx = bx[0]; ngy = bx[1]; ngr = bx[2];
        }
    }

    int st = 0;
    for (int p = p0; p < P; p += TW) {
        // wait until this stage's pair has landed
        cp_wait<NSTAGE - 1>();

        const float4* stg = wbase4 + st * 256;

        // ---- noobj total: 8 conflict-free LDS.128 covering the 4KB stage ----
#pragma unroll
        for (int k = 0; k < 8; k++) {
            float4 v = stg[lane + 32 * k];
            nsum = fmaf(v.w, v.w, nsum);
        }

        // current labels (prefetched last iteration)
        int2 rc = nrc;
        float gx = ngx, gy = ngy, gr = ngr;
        bool valid = nval;

        // prefetch next pair's labels
        nval = false;
        {
            int pn = p + TW;
            if (pn < P) {
                int bb = 2 * pn + half;
                if (bb < B) {
                    nval = true;
                    nrc = reinterpret_cast<const int2*>(label_rc)[(size_t)bb * 16 + li];
                    const float* bx = label_box + ((size_t)bb * 16 + li) * 3;
                    ngx = bx[0]; ngy = bx[1]; ngr = bx[2];
                }
            }
        }

        // ---- full-warp label section: A on lanes 0-15, B on lanes 16-31 ----
        int cell = valid ? (rc.x * 8 + rc.y) : 0;                // 0..63
        int enc  = valid ? (cell + (half << 6)) : (128 + lane);  // distinct per batch
        unsigned peers = __match_any_sync(0xffffffffu, enc);
        bool leader = (lane == (__ffs(peers) - 1));

        const float4* src = stg + (half << 7);
        float4 A = src[cell * 2];
        float4 C = src[cell * 2 + 1];

        // stage st fully read — refill it for pair p + NSTAGE*TW
        issue(st, p + NSTAGE * TW);

        float iou1 = bbox_iou(A.x, A.y, A.z, gx, gy, gr);
        float iou2 = bbox_iou(C.x, C.y, C.z, gx, gy, gr);
        bool swp = iou2 > iou1;

        float cx   = swp ? C.x : A.x;
        float cy   = swp ? C.y : A.y;
        float cr   = swp ? C.z : A.z;
        float conf = swp ? C.w : A.w;
        float ucnf = swp ? A.w : C.w;
        float big  = swp ? iou2 : iou1;
        float sml  = swp ? iou1 : iou2;

        if (valid) {
            float dx = cx - gx, dy = cy - gy, dr = cr - gr;
            acc += LAMBDA_COORD * (dx * dx + dy * dy + dr * dr);
            float dc = big - conf;
            acc += dc * dc;
            float du = sml - ucnf;
            acc += LAMBDA_NOOBJ * du * du;
            if (leader) {       // distinct object cell: remove from noobj total
                nsub = fmaf(A.w, A.w, nsub);
                nsub = fmaf(C.w, C.w, nsub);
            }
        }

        st ^= 1;
    }

    acc += LAMBDA_NOOBJ * (nsum - nsub);

    // drain own async groups; barrier before aliasing dsh as reduction scratch
    cp_wait<0>();
    __syncthreads();

    double* blocksum = reinterpret_cast<double*>(dsh);   // 6 doubles
    int*    islast_p = reinterpret_cast<int*>(dsh + 12); // 1 int after 48 bytes

    // warp reduce (float)
#pragma unroll
    for (int o = 16; o > 0; o >>= 1)
        acc += __shfl_xor_sync(0xffffffffu, acc, o);
    if (lane == 0) blocksum[warp] = (double)acc;
    __syncthreads();

    if (threadIdx.x == 0) {
        double s = 0.0;
#pragma unroll
        for (int w = 0; w < WPB; w++) s += blocksum[w];
        g_partial[blockIdx.x] = s;
        __threadfence();
        unsigned ticket = atomicAdd(&g_count, 1u);
        *islast_p = (ticket == (unsigned)(gridDim.x - 1)) ? 1 : 0;
    }
    __syncthreads();

    // ---- last block folds partials (deterministic fixed order) ----
    if (*islast_p) {
        double s = 0.0;
        for (int i = threadIdx.x; i < NBLK; i += WPB * 32)
            s += *((volatile double*)&g_partial[i]);
        // warp-level double reduce, then 6 partials
#pragma unroll
        for (int o = 16; o > 0; o >>= 1)
            s += __shfl_xor_sync(0xffffffffu, s, o);
        __syncthreads();   // blocksum free for reuse (tid0 consumed it above)
        if (lane == 0) blocksum[warp] = s;
        __syncthreads();
        if (threadIdx.x == 0) {
            double t = 0.0;
#pragma unroll
            for (int w = 0; w < WPB; w++) t += blocksum[w];
            out[0] = (float)(t / (double)B);
            g_count = 0;  // reset for next graph replay
        }
    }
}

extern "C" void kernel_launch(void* const* d_in, const int* in_sizes, int n_in,
                              void* d_out, int out_size) {
    const float* pred      = (const float*)d_in[0];
    const int*   label_rc  = (const int*)d_in[1];
    const float* label_box = (const float*)d_in[2];
    float* out = (float*)d_out;

    int B = in_sizes[0] / 512;  // pred is [B, 8, 8, 8]
    size_t smem = (size_t)WPB * NSTAGE * STAGE_BYTES;  // 48 KB exactly

    yolo_loss_kernel<<<NBLK, WPB * 32, smem>>>(pred, label_rc, label_box, B, out);
}

// round 13
// speedup vs baseline: 1.0523x; 1.0523x over previous
#include <cuda_runtime.h>
#include <cuda_bf16.h>
#include <cstdint>

#define LAMBDA_COORD 5.0f
#define LAMBDA_NOOBJ 0.5f
#define EPS 1e-9f
#define WPB 8                   // warps per block (256 threads)
#define BPSM 4                  // blocks per SM (cap 64 regs)
#define NBLK (148 * BPSM)       // one resident wave = 592 blocks

__device__ double g_partial[NBLK];
__device__ unsigned g_count = 0;

__device__ __forceinline__ float bbox_iou(float px, float py, float pr,
                                          float gx, float gy, float gr) {
    float l1 = px - pr, r1 = px + pr, t1 = py - pr, b1 = py + pr;
    float l2 = gx - gr, r2 = gx + gr, t2 = gy - gr, b2 = gy + gr;
    float iw = fmaxf(fminf(r1, r2) - fmaxf(l1, l2), 0.0f);
    float ih = fmaxf(fminf(b1, b2) - fmaxf(t1, t2), 0.0f);
    float inter = iw * ih;
    float a1 = (r1 - l1) * (b1 - t1);
    float a2 = (r2 - l2) * (b2 - t2);
    return inter / (a1 + a2 - inter + EPS);
}

__global__ void __launch_bounds__(WPB * 32, BPSM)
yolo_loss_kernel(const float* __restrict__ pred,
                 const int*   __restrict__ label_rc,
                 const float* __restrict__ label_box,
                 int B, float* __restrict__ out) {
    __shared__ double blocksum[WPB];
    __shared__ int islast;

    const int warp = threadIdx.x >> 5;
    const int lane = threadIdx.x & 31;
    const int TW = NBLK * WPB;           // total warps = 4736
    const int P = (B + 1) >> 1;          // batch pairs
    const int p0 = blockIdx.x * WPB + warp;

    const int li   = lane & 15;          // label index within batch
    const int half = lane >> 4;          // 0 = batch A, 1 = batch B

    const float4 zero4 = make_float4(0.f, 0.f, 0.f, 0.f);

    float acc  = 0.0f;   // coord + conf (weighted)
    float nsum = 0.0f;   // c3^2+c7^2 over ALL cells
    float nsub = 0.0f;   // over distinct object cells

    // ---- label prefetch for first pair (distance-1 pipeline) ----
    int2 nrc = make_int2(0, 0);
    float ngx = 0.f, ngy = 0.f, ngr = 0.f;
    bool nval = false;
    if (p0 < P) {
        int bb = 2 * p0 + half;
        if (bb < B) {
            nval = true;
            nrc = reinterpret_cast<const int2*>(label_rc)[(size_t)bb * 16 + li];
            const float* bx = label_box + ((size_t)bb * 16 + li) * 3;
            ngx = bx[0]; ngy = bx[1]; ngr = bx[2];
        }
    }

    for (int p = p0; p < P; p += TW) {
        const float4* pa = reinterpret_cast<const float4*>(pred) + (size_t)p * 256;
        const bool fullpair = (2 * p + 1 < B);

        // ---- stream the 4KB pair directly into registers (8 LDG.128) ----
        float4 v0 = pa[lane];
        float4 v1 = pa[lane + 32];
        float4 v2 = pa[lane + 64];
        float4 v3 = pa[lane + 96];
        float4 v4 = zero4, v5 = zero4, v6 = zero4, v7 = zero4;
        if (fullpair) {
            v4 = pa[lane + 128];
            v5 = pa[lane + 160];
            v6 = pa[lane + 192];
            v7 = pa[lane + 224];
        }

        // ---- current labels (prefetched) ----
        int2 rc = nrc;
        float gx = ngx, gy = ngy, gr = ngr;
        bool valid = nval;

        // ---- gather this label's cell DIRECTLY from gmem (same lines as
        //      the stream loads above — L1/MSHR merge, latency shared) ----
        int cell = valid ? (rc.x * 8 + rc.y) : 0;
        int bb = 2 * p + half;
        if (bb >= B) bb = 2 * p;   // safe address for invalid lanes
        const float4* cellp = reinterpret_cast<const float4*>(
                                  pred + (size_t)bb * 512) + cell * 2;
        float4 A = cellp[0];   // p0..p3
        float4 C = cellp[1];   // q0..q7

        // ---- prefetch next pair's labels ----
        nval = false;
        {
            int pn = p + TW;
            if (pn < P) {
                int nbb = 2 * pn + half;
                if (nbb < B) {
                    nval = true;
                    nrc = reinterpret_cast<const int2*>(label_rc)[(size_t)nbb * 16 + li];
                    const float* bx = label_box + ((size_t)nbb * 16 + li) * 3;
                    ngx = bx[0]; ngy = bx[1]; ngr = bx[2];
                }
            }
        }

        // ---- dedupe object cells across the pair ----
        int enc = valid ? (cell + (half << 6)) : (128 + lane);
        unsigned peers = __match_any_sync(0xffffffffu, enc);
        bool leader = (lane == (__ffs(peers) - 1));

        // ---- noobj total: unconditional FMAs on the stream data ----
        nsum = fmaf(v0.w, v0.w, nsum);
        nsum = fmaf(v1.w, v1.w, nsum);
        nsum = fmaf(v2.w, v2.w, nsum);
        nsum = fmaf(v3.w, v3.w, nsum);
        nsum = fmaf(v4.w, v4.w, nsum);
        nsum = fmaf(v5.w, v5.w, nsum);
        nsum = fmaf(v6.w, v6.w, nsum);
        nsum = fmaf(v7.w, v7.w, nsum);

        // ---- coord + conf losses (full warp: A-batch lanes 0-15, B 16-31) ----
        float iou1 = bbox_iou(A.x, A.y, A.z, gx, gy, gr);
        float iou2 = bbox_iou(C.x, C.y, C.z, gx, gy, gr);
        bool swp = iou2 > iou1;

        float cx   = swp ? C.x : A.x;
        float cy   = swp ? C.y : A.y;
        float cr   = swp ? C.z : A.z;
        float conf = swp ? C.w : A.w;
        float ucnf = swp ? A.w : C.w;
        float big  = swp ? iou2 : iou1;
        float sml  = swp ? iou1 : iou2;

        if (valid) {
            float dx = cx - gx, dy = cy - gy, dr = cr - gr;
            acc += LAMBDA_COORD * (dx * dx + dy * dy + dr * dr);
            float dc = big - conf;
            acc += dc * dc;
            float du = sml - ucnf;
            acc += LAMBDA_NOOBJ * du * du;
            if (leader) {       // distinct object cell: remove from noobj total
                nsub = fmaf(A.w, A.w, nsub);
                nsub = fmaf(C.w, C.w, nsub);
            }
        }
    }

    acc += LAMBDA_NOOBJ * (nsum - nsub);

    // ---- warp reduce -> block reduce ----
#pragma unroll
    for (int o = 16; o > 0; o >>= 1)
        acc += __shfl_xor_sync(0xffffffffu, acc, o);
    if (lane == 0) blocksum[warp] = (double)acc;
    __syncthreads();

    if (threadIdx.x == 0) {
        double s = 0.0;
#pragma unroll
        for (int w = 0; w < WPB; w++) s += blocksum[w];
        g_partial[blockIdx.x] = s;
        __threadfence();
        unsigned ticket = atomicAdd(&g_count, 1u);
        islast = (ticket == (unsigned)(gridDim.x - 1)) ? 1 : 0;
    }
    __syncthreads();

    // ---- last block folds partials (deterministic fixed order) ----
    if (islast) {
        double s = 0.0;
        for (int i = threadIdx.x; i < NBLK; i += WPB * 32)
            s += *((volatile double*)&g_partial[i]);
#pragma unroll
        for (int o = 16; o > 0; o >>= 1)
            s += __shfl_xor_sync(0xffffffffu, s, o);
        __syncthreads();   // blocksum reusable now
        if (lane == 0) blocksum[warp] = s;
        __syncthreads();
        if (threadIdx.x == 0) {
            double t = 0.0;
#pragma unroll
            for (int w = 0; w < WPB; w++) t += blocksum[w];
            out[0] = (float)(t / (double)B);
            g_count = 0;  // reset for next graph replay
        }
    }
}

extern "C" void kernel_launch(void* const* d_in, const int* in_sizes, int n_in,
                              void* d_out, int out_size) {
    const float* pred      = (const float*)d_in[0];
    const int*   label_rc  = (const int*)d_in[1];
    const float* label_box = (const float*)d_in[2];
    float* out = (float*)d_out;

    int B = in_sizes[0] / 512;  // pred is [B, 8, 8, 8]

    yolo_loss_kernel<<<NBLK, WPB * 32>>>(pred, label_rc, label_box, B, out);
}